// round 1
// baseline (speedup 1.0000x reference)
#include <cuda_runtime.h>

#define THREADS 256
#define WARPS (THREADS / 32)
#define GRID 592            // 148 SMs * 4 resident blocks @ 256 threads -> one wave
#define D 128               // feature dim (f32), = 32 lanes * float4

__global__ void zero_out_kernel(float* __restrict__ out, int n) {
    int i = blockIdx.x * blockDim.x + threadIdx.x;
    if (i < n) out[i] = 0.0f;
}

__global__ __launch_bounds__(THREADS) void segsum_kernel(
    const float4* __restrict__ feat4,      // [rows, 32] float4
    const int*    __restrict__ sids,       // [rows]
    float*        __restrict__ out,        // [num_segments, 128]
    int rows, int rows_per_block)
{
    const int lane = threadIdx.x & 31;
    const int warp = threadIdx.x >> 5;

    int row0    = blockIdx.x * rows_per_block;
    int row_end = row0 + rows_per_block;
    if (row_end > rows) row_end = rows;

    int r = row0 + warp;
    if (r >= row_end) return;

    float4 acc = make_float4(0.f, 0.f, 0.f, 0.f);
    int cur = __ldg(&sids[r]);

    #pragma unroll 4
    for (; r < row_end; r += WARPS) {
        float4 v  = __ldg(&feat4[(long long)r * 32 + lane]);
        int   sid = __ldg(&sids[r]);
        if (sid != cur) {
            float* o = out + (long long)cur * D + lane * 4;
            atomicAdd(o + 0, acc.x);
            atomicAdd(o + 1, acc.y);
            atomicAdd(o + 2, acc.z);
            atomicAdd(o + 3, acc.w);
            cur = sid;
            acc = v;
        } else {
            acc.x += v.x; acc.y += v.y; acc.z += v.z; acc.w += v.w;
        }
    }

    float* o = out + (long long)cur * D + lane * 4;
    atomicAdd(o + 0, acc.x);
    atomicAdd(o + 1, acc.y);
    atomicAdd(o + 2, acc.z);
    atomicAdd(o + 3, acc.w);
}

extern "C" void kernel_launch(void* const* d_in, const int* in_sizes, int n_in,
                              void* d_out, int out_size)
{
    const float4* feat4 = (const float4*)d_in[0];   // feat [1e6, 128] f32
    const int*    sids  = (const int*)d_in[1];      // segment_ids [1e6] i32
    float*        out   = (float*)d_out;            // [4096, 128] f32

    const int rows = in_sizes[0] / D;

    // Zero-init output (d_out is poisoned before timing).
    {
        int n = out_size;
        int blocks = (n + THREADS - 1) / THREADS;
        zero_out_kernel<<<blocks, THREADS>>>(out, n);
    }

    // Contiguous chunk per block, chunk size multiple of WARPS.
    int rpb = (rows + GRID - 1) / GRID;
    rpb = (rpb + WARPS - 1) & ~(WARPS - 1);
    int grid = (rows + rpb - 1) / rpb;

    segsum_kernel<<<grid, THREADS>>>(feat4, sids, out, rows, rpb);
}

// round 6
// speedup vs baseline: 1.4705x; 1.4705x over previous
#include <cuda_runtime.h>

#define THREADS 256
#define WARPS   (THREADS / 32)
#define D       128                  // feature dim (f32) = 32 lanes * float4
#define TARGET_BLOCKS 1184           // 148 SMs * 8 blocks -> 64 warps/SM (full occ)
#define UNROLL  4

__global__ void zero_out_kernel(float* __restrict__ out, int n) {
    int i = blockIdx.x * blockDim.x + threadIdx.x;
    if (i < n) out[i] = 0.0f;
}

__device__ __forceinline__ void flush(float* __restrict__ out, int seg, int lane, float4 acc) {
    float* o = out + (long long)seg * D + lane * 4;
    atomicAdd(o + 0, acc.x);
    atomicAdd(o + 1, acc.y);
    atomicAdd(o + 2, acc.z);
    atomicAdd(o + 3, acc.w);
}

__device__ __forceinline__ void merge(int s, float4 v, int& cur, float4& acc,
                                      float* __restrict__ out, int lane) {
    if (__builtin_expect(s != cur, 0)) {
        flush(out, cur, lane, acc);
        cur = s;
        acc = v;
    } else {
        acc.x += v.x; acc.y += v.y; acc.z += v.z; acc.w += v.w;
    }
}

__global__ __launch_bounds__(THREADS) void segsum_kernel(
    const float4* __restrict__ feat4,      // [rows, 32] float4
    const int*    __restrict__ sids,       // [rows]
    float*        __restrict__ out,        // [num_segments, 128]
    int rows, int rows_per_block)
{
    const int lane = threadIdx.x & 31;
    const int warp = threadIdx.x >> 5;

    int row0    = blockIdx.x * rows_per_block;
    int row_end = row0 + rows_per_block;
    if (row_end > rows) row_end = rows;

    int r = row0 + warp;
    if (r >= row_end) return;

    float4 acc = make_float4(0.f, 0.f, 0.f, 0.f);
    int cur = __ldg(&sids[r]);

    // Unrolled main loop: all UNROLL loads issued back-to-back (MLP), then merge.
    for (; r + (UNROLL - 1) * WARPS < row_end; r += UNROLL * WARPS) {
        float4 v0 = __ldcs(&feat4[(long long)(r + 0 * WARPS) * 32 + lane]);
        float4 v1 = __ldcs(&feat4[(long long)(r + 1 * WARPS) * 32 + lane]);
        float4 v2 = __ldcs(&feat4[(long long)(r + 2 * WARPS) * 32 + lane]);
        float4 v3 = __ldcs(&feat4[(long long)(r + 3 * WARPS) * 32 + lane]);
        int s0 = __ldcs(&sids[r + 0 * WARPS]);
        int s1 = __ldcs(&sids[r + 1 * WARPS]);
        int s2 = __ldcs(&sids[r + 2 * WARPS]);
        int s3 = __ldcs(&sids[r + 3 * WARPS]);

        merge(s0, v0, cur, acc, out, lane);
        merge(s1, v1, cur, acc, out, lane);
        merge(s2, v2, cur, acc, out, lane);
        merge(s3, v3, cur, acc, out, lane);
    }

    // Remainder
    for (; r < row_end; r += WARPS) {
        float4 v = __ldcs(&feat4[(long long)r * 32 + lane]);
        int    s = __ldcs(&sids[r]);
        merge(s, v, cur, acc, out, lane);
    }

    flush(out, cur, lane, acc);
}

extern "C" void kernel_launch(void* const* d_in, const int* in_sizes, int n_in,
                              void* d_out, int out_size)
{
    const float4* feat4 = (const float4*)d_in[0];   // feat [1e6, 128] f32
    const int*    sids  = (const int*)d_in[1];      // segment_ids [1e6] i32
    float*        out   = (float*)d_out;            // [4096, 128] f32

    const int rows = in_sizes[0] / D;

    // Zero-init output (d_out is poisoned before timing).
    {
        int blocks = (out_size + THREADS - 1) / THREADS;
        zero_out_kernel<<<blocks, THREADS>>>(out, out_size);
    }

    // Contiguous chunk per block, chunk size multiple of WARPS.
    int rpb = (rows + TARGET_BLOCKS - 1) / TARGET_BLOCKS;
    rpb = (rpb + WARPS - 1) & ~(WARPS - 1);
    int grid = (rows + rpb - 1) / rpb;

    segsum_kernel<<<grid, THREADS>>>(feat4, sids, out, rows, rpb);
}

// round 7
// speedup vs baseline: 1.4778x; 1.0050x over previous
#include <cuda_runtime.h>

#define THREADS 256
#define WARPS   (THREADS / 32)
#define D       128                  // feature dim (f32) = 32 lanes * float4
#define BLOCKS_PER_SM 6
#define NUM_SMS 148
#define TARGET_BLOCKS (NUM_SMS * BLOCKS_PER_SM)   // 888 -> exactly one wave
#define UNROLL  4

__global__ void zero_out_kernel(float* __restrict__ out, int n) {
    int i = blockIdx.x * blockDim.x + threadIdx.x;
    if (i < n) out[i] = 0.0f;
}

__device__ __forceinline__ void flush(float* __restrict__ out, int seg, int lane, float4 acc) {
    float* o = out + (long long)seg * D + lane * 4;
    atomicAdd(o + 0, acc.x);
    atomicAdd(o + 1, acc.y);
    atomicAdd(o + 2, acc.z);
    atomicAdd(o + 3, acc.w);
}

__device__ __forceinline__ void merge(int s, float4 v, int& cur, float4& acc,
                                      float* __restrict__ out, int lane) {
    if (__builtin_expect(s != cur, 0)) {
        flush(out, cur, lane, acc);
        cur = s;
        acc = v;
    } else {
        acc.x += v.x; acc.y += v.y; acc.z += v.z; acc.w += v.w;
    }
}

__global__ __launch_bounds__(THREADS, BLOCKS_PER_SM) void segsum_kernel(
    const float4* __restrict__ feat4,      // [rows, 32] float4
    const int*    __restrict__ sids,       // [rows]
    float*        __restrict__ out,        // [num_segments, 128]
    int rows, int rows_per_block)
{
    const int lane = threadIdx.x & 31;
    const int warp = threadIdx.x >> 5;

    int row0    = blockIdx.x * rows_per_block;
    int row_end = row0 + rows_per_block;
    if (row_end > rows) row_end = rows;

    int r = row0 + warp;
    if (r >= row_end) return;

    float4 acc = make_float4(0.f, 0.f, 0.f, 0.f);
    int cur = __ldg(&sids[r]);

    // Unrolled main loop: all UNROLL loads issued back-to-back (MLP), then merge.
    for (; r + (UNROLL - 1) * WARPS < row_end; r += UNROLL * WARPS) {
        float4 v0 = __ldcs(&feat4[(long long)(r + 0 * WARPS) * 32 + lane]);
        float4 v1 = __ldcs(&feat4[(long long)(r + 1 * WARPS) * 32 + lane]);
        float4 v2 = __ldcs(&feat4[(long long)(r + 2 * WARPS) * 32 + lane]);
        float4 v3 = __ldcs(&feat4[(long long)(r + 3 * WARPS) * 32 + lane]);
        int s0 = __ldcs(&sids[r + 0 * WARPS]);
        int s1 = __ldcs(&sids[r + 1 * WARPS]);
        int s2 = __ldcs(&sids[r + 2 * WARPS]);
        int s3 = __ldcs(&sids[r + 3 * WARPS]);

        merge(s0, v0, cur, acc, out, lane);
        merge(s1, v1, cur, acc, out, lane);
        merge(s2, v2, cur, acc, out, lane);
        merge(s3, v3, cur, acc, out, lane);
    }

    // Remainder
    for (; r < row_end; r += WARPS) {
        float4 v = __ldcs(&feat4[(long long)r * 32 + lane]);
        int    s = __ldcs(&sids[r]);
        merge(s, v, cur, acc, out, lane);
    }

    flush(out, cur, lane, acc);
}

extern "C" void kernel_launch(void* const* d_in, const int* in_sizes, int n_in,
                              void* d_out, int out_size)
{
    const float4* feat4 = (const float4*)d_in[0];   // feat [1e6, 128] f32
    const int*    sids  = (const int*)d_in[1];      // segment_ids [1e6] i32
    float*        out   = (float*)d_out;            // [4096, 128] f32

    const int rows = in_sizes[0] / D;

    // Zero-init output (d_out is poisoned before timing).
    {
        int blocks = (out_size + THREADS - 1) / THREADS;
        zero_out_kernel<<<blocks, THREADS>>>(out, out_size);
    }

    // Contiguous chunk per block, chunk size multiple of WARPS,
    // grid sized to exactly one full wave (no quantization tail).
    int rpb = (rows + TARGET_BLOCKS - 1) / TARGET_BLOCKS;
    rpb = (rpb + WARPS - 1) & ~(WARPS - 1);
    int grid = (rows + rpb - 1) / rpb;

    segsum_kernel<<<grid, THREADS>>>(feat4, sids, out, rows, rpb);
}